// round 10
// baseline (speedup 1.0000x reference)
#include <cuda_runtime.h>
#include <cuda_fp16.h>
#include <cstdint>

#define T_LEN 4096
#define E_DIM 1024
#define H_NUM 16
#define HD    64
#define NBX_SCORES 4     // column splits in scores kernel
#define NT_SC 8          // K-tiles per scores block

// Scratch (allocation-free rule: __device__ globals)
__device__ __half g_Q  [(long)H_NUM * T_LEN * HD];
__device__ __half g_K  [(long)H_NUM * T_LEN * HD];
__device__ __half g_Vt [(long)H_NUM * HD * T_LEN];
__device__ __half g_P  [(long)H_NUM * T_LEN * T_LEN];
__device__ __half g_CTX[(long)T_LEN * E_DIM];
__device__ __half g_W16[(long)4 * E_DIM * E_DIM];     // fp16 weights: [wq|wk|wv|ow]
__device__ float  g_RSP[(long)H_NUM * T_LEN * NBX_SCORES];
__device__ float  g_INV[(long)H_NUM * T_LEN];

__device__ __forceinline__ float ex2(float x) {
    float r;
    asm("ex2.approx.f32 %0, %1;" : "=f"(r) : "f"(x));
    return r;
}
__device__ __forceinline__ uint32_t smem_u32(const void* p) {
    return (uint32_t)__cvta_generic_to_shared(p);
}
__device__ __forceinline__ void ldsm_x4(uint32_t r[4], uint32_t addr) {
    asm volatile("ldmatrix.sync.aligned.m8n8.x4.shared.b16 {%0,%1,%2,%3}, [%4];"
        : "=r"(r[0]), "=r"(r[1]), "=r"(r[2]), "=r"(r[3]) : "r"(addr));
}
__device__ __forceinline__ void cp_async16(uint32_t saddr, const void* gaddr) {
    asm volatile("cp.async.cg.shared.global [%0], [%1], 16;" :: "r"(saddr), "l"(gaddr));
}
__device__ __forceinline__ void cp_commit() { asm volatile("cp.async.commit_group;"); }
template<int N>
__device__ __forceinline__ void cp_wait() {
    asm volatile("cp.async.wait_group %0;" :: "n"(N));
}

__device__ __forceinline__ void mma_f16(float c[4],
    uint32_t a0, uint32_t a1, uint32_t a2, uint32_t a3,
    uint32_t b0, uint32_t b1)
{
    asm volatile(
        "mma.sync.aligned.m16n8k16.row.col.f32.f16.f16.f32 "
        "{%0,%1,%2,%3}, {%4,%5,%6,%7}, {%8,%9}, {%0,%1,%2,%3};"
        : "+f"(c[0]), "+f"(c[1]), "+f"(c[2]), "+f"(c[3])
        : "r"(a0), "r"(a1), "r"(a2), "r"(a3), "r"(b0), "r"(b1));
}

#define LOG2E 1.4426950408889634f
#define PSHIFT 2.0f

// ===========================================================================
// Scores: 3-stage cp.async pipeline, Q fragments register-resident,
// STG.128 P stores via quad transpose. grid (4, 32, 16), 256 thr.
// ===========================================================================
__global__ __launch_bounds__(256, 2)
void scores_k(const __half* __restrict__ Q, const __half* __restrict__ Kp,
              __half* __restrict__ P, float* __restrict__ rsp)
{
    __shared__ __half Qs[128][72];
    __shared__ __half Ks[3][128][72];
    __shared__ float  srs[512];

    const int tid  = threadIdx.x;
    const int warp = tid >> 5, lane = tid & 31;
    const int gid = lane >> 2, tg = lane & 3;
    const int wm0 = (warp >> 2) * 64;
    const int wn0 = (warp & 3) * 32;
    const int gm0 = blockIdx.y * 128;
    const int cbase = blockIdx.x * (NT_SC * 128);

    const __half* Ah = Q  + (long)blockIdx.z * T_LEN * HD + (long)gm0 * HD;
    const __half* Kh = Kp + (long)blockIdx.z * T_LEN * HD + (long)cbase * HD;

    int lm[4], lk[4];
#pragma unroll
    for (int i = 0; i < 4; i++) {
        const int idx = (tid + i * 256) * 8;
        lm[i] = idx >> 6; lk[i] = idx & 63;
    }
    auto prefetchK = [&](int nt, int buf) {
#pragma unroll
        for (int i = 0; i < 4; i++)
            cp_async16(smem_u32(&Ks[buf][lm[i]][lk[i]]),
                       Kh + ((long)nt * 128 + lm[i]) * HD + lk[i]);
    };

#pragma unroll
    for (int i = 0; i < 4; i++)
        cp_async16(smem_u32(&Qs[lm[i]][lk[i]]), Ah + (long)lm[i] * HD + lk[i]);
    prefetchK(0, 0); cp_commit();
    prefetchK(1, 1); cp_commit();
    prefetchK(2, 2); cp_commit();
    cp_wait<2>();            // Q + K0 ready
    __syncthreads();

    // Q fragments once
    uint32_t af[4][4][4];
#pragma unroll
    for (int i = 0; i < 4; i++) {
        const uint32_t a = smem_u32(&Qs[wm0 + i*16 + (lane & 15)][(lane >> 4) * 8]);
#pragma unroll
        for (int ks = 0; ks < 4; ks++) ldsm_x4(af[ks][i], a + ks * 32);
    }

    uint32_t bAddr[3][2];
#pragma unroll
    for (int buf = 0; buf < 3; buf++)
#pragma unroll
        for (int jp = 0; jp < 2; jp++)
            bAddr[buf][jp] = smem_u32(
                &Ks[buf][wn0 + jp*16 + (lane & 7) + ((lane >> 4) << 3)]
                        [((lane >> 3) & 1) * 8]);

    float rsum[4][2];
#pragma unroll
    for (int i = 0; i < 4; i++) { rsum[i][0] = 0.f; rsum[i][1] = 0.f; }

    __half* Ch = P + (long)blockIdx.z * T_LEN * T_LEN;

#pragma unroll 1
    for (int nt = 0; nt < NT_SC; nt++) {
        const int buf = nt % 3;

        float acc[4][4][4];
#pragma unroll
        for (int i = 0; i < 4; i++)
#pragma unroll
            for (int j = 0; j < 4; j++)
#pragma unroll
                for (int q = 0; q < 4; q++) acc[i][j][q] = 0.0f;

#pragma unroll
        for (int ks = 0; ks < 4; ks++) {
            uint32_t bq[2][4];
#pragma unroll
            for (int jp = 0; jp < 2; jp++)
                ldsm_x4(bq[jp], bAddr[buf][jp] + ks * 32);
#pragma unroll
            for (int i = 0; i < 4; i++)
#pragma unroll
                for (int j = 0; j < 4; j++)
                    mma_f16(acc[i][j], af[ks][i][0], af[ks][i][1],
                            af[ks][i][2], af[ks][i][3],
                            bq[j >> 1][(j & 1) * 2], bq[j >> 1][(j & 1) * 2 + 1]);
        }

        __syncthreads();                    // all warps done reading Ks[buf]
        if (nt + 3 < NT_SC) { prefetchK(nt + 3, buf); cp_commit(); }

        // epilogue: exp -> quad-transpose -> STG.128 (overlaps prefetch)
        const int n0t = cbase + nt * 128;
#pragma unroll
        for (int i = 0; i < 4; i++) {
#pragma unroll
            for (int h2 = 0; h2 < 2; h2++) {
                uint32_t hp[4];
#pragma unroll
                for (int j = 0; j < 4; j++) {
                    float v0 = ex2(fmaf(acc[i][j][h2*2 + 0], LOG2E, PSHIFT));
                    float v1 = ex2(fmaf(acc[i][j][h2*2 + 1], LOG2E, PSHIFT));
                    rsum[i][h2] += v0 + v1;
                    __half2 h = __floats2half2_rn(v0, v1);
                    hp[j] = *(uint32_t*)&h;
                }
                // 4x4 transpose across quad lanes (xor 1 then xor 2)
                {
                    uint32_t t, r;
                    t = (tg & 1) ? hp[0] : hp[1];
                    r = __shfl_xor_sync(0xffffffffu, t, 1);
                    if (tg & 1) hp[0] = r; else hp[1] = r;
                    t = (tg & 1) ? hp[2] : hp[3];
                    r = __shfl_xor_sync(0xffffffffu, t, 1);
                    if (tg & 1) hp[2] = r; else hp[3] = r;
                    t = (tg & 2) ? hp[0] : hp[2];
                    r = __shfl_xor_sync(0xffffffffu, t, 2);
                    if (tg & 2) hp[0] = r; else hp[2] = r;
                    t = (tg & 2) ? hp[1] : hp[3];
                    r = __shfl_xor_sync(0xffffffffu, t, 2);
                    if (tg & 2) hp[1] = r; else hp[3] = r;
                }
                const int m = gm0 + wm0 + i * 16 + gid + h2 * 8;
                const int n = n0t + wn0 + tg * 8;
                *(uint4*)(Ch + (long)m * T_LEN + n) =
                    make_uint4(hp[0], hp[1], hp[2], hp[3]);
            }
        }

        if (nt + 1 < NT_SC) {
            if (nt < 5)      cp_wait<2>();
            else if (nt == 5) cp_wait<1>();
            else              cp_wait<0>();
            __syncthreads();                // next buffer visible to all
        }
    }

    // row-sum partials
#pragma unroll
    for (int i = 0; i < 4; i++)
#pragma unroll
        for (int h2 = 0; h2 < 2; h2++)
#pragma unroll
            for (int o = 1; o < 4; o <<= 1)
                rsum[i][h2] += __shfl_xor_sync(0xffffffffu, rsum[i][h2], o);
    if (tg == 0) {
        const int wn = warp & 3;
#pragma unroll
        for (int i = 0; i < 4; i++)
#pragma unroll
            for (int h2 = 0; h2 < 2; h2++)
                srs[wn * 128 + wm0 + i * 16 + h2 * 8 + gid] = rsum[i][h2];
    }
    __syncthreads();
    if (tid < 128) {
        float s = srs[tid] + srs[128 + tid] + srs[256 + tid] + srs[384 + tid];
        rsp[((long)blockIdx.z * T_LEN + gm0 + tid) * NBX_SCORES + blockIdx.x] = s;
    }
}

// ===========================================================================
// Generic fp16-MMA GEMM, double-buffered, BK=32, LDSM fragment loads.
// ===========================================================================
template<int BM, int BN, int WARPS_M, int WARPS_N,
         int EPI, bool AH, bool BH, bool NORMROW, bool CH>
__global__ __launch_bounds__(WARPS_M*WARPS_N*32)
void gemm_k(const void* __restrict__ Av, const void* __restrict__ Bv,
            const float* __restrict__ bias, void* __restrict__ Cv,
            const float* __restrict__ rowinv,
            int M, int N, int K, int ldc,
            long aH, long bH, long cH, long riH, float scale)
{
    constexpr int THREADS = WARPS_M*WARPS_N*32;
    constexpr int BK = 32;
    constexpr int WM = BM/WARPS_M, WN = BN/WARPS_N;
    constexpr int MT = WM/16, NT = WN/8;
    static_assert(NT % 2 == 0, "NT must be even");

    const float*  Af  = (const float*) Av + (AH ? 0 : blockIdx.z * aH);
    const __half* Ahp = (const __half*)Av + (AH ? blockIdx.z * aH : 0);
    const float*  Bf  = (const float*) Bv + (BH ? 0 : blockIdx.z * bH);
    const __half* Bhp = (const __half*)Bv + (BH ? blockIdx.z * bH : 0);
    float*  Cf  = (float*) Cv + (CH ? 0 : blockIdx.z * cH);
    __half* Chp = (__half*)Cv + (CH ? blockIdx.z * cH : 0);
    if (NORMROW) rowinv += blockIdx.z * riH;

    __shared__ __half As[2][BM][40];
    __shared__ __half Bs[2][BN][40];

    const int tid  = threadIdx.x;
    const int warp = tid >> 5, lane = tid & 31;
    const int wm0 = (warp / WARPS_N) * WM;
    const int wn0 = (warp % WARPS_N) * WN;
    const int gid = lane >> 2, tg = lane & 3;
    const int gm0 = blockIdx.y * BM, gn0 = blockIdx.x * BN;

    constexpr int AC = AH ? BM*BK/(THREADS*8) : BM*BK/(THREADS*4);
    constexpr int BC = BH ? BN*BK/(THREADS*8) : BN*BK/(THREADS*4);
    int am[AC], ak[AC], bn[BC], bk[BC];
#pragma unroll
    for (int i = 0; i < AC; i++) {
        int idx = (tid + i*THREADS) * (AH ? 8 : 4);
        am[i] = idx / BK; ak[i] = idx % BK;
    }
#pragma unroll
    for (int i = 0; i < BC; i++) {
        int idx = (tid + i*THREADS) * (BH ? 8 : 4);
        bn[i] = idx / BK; bk[i] = idx % BK;
    }

    constexpr uint32_t A_BUF = BM * 40 * 2;
    constexpr uint32_t B_BUF = BN * 40 * 2;
    uint32_t aAddr0[MT], bAddr0[NT/2];
#pragma unroll
    for (int i = 0; i < MT; i++)
        aAddr0[i] = smem_u32(&As[0][wm0 + i*16 + (lane & 15)][(lane >> 4) * 8]);
#pragma unroll
    for (int jp = 0; jp < NT/2; jp++)
        bAddr0[jp] = smem_u32(&Bs[0][wn0 + jp*16 + (lane & 7) + ((lane >> 4) << 3)]
                                 [((lane >> 3) & 1) * 8]);

    uint4  ra16[AC], rb16[BC];
    float4 ra32[AC], rb32[BC];
    auto loadg = [&](int k0) {
#pragma unroll
        for (int i = 0; i < AC; i++) {
            if (AH) ra16[i] = *(const uint4*)(Ahp + (long)(gm0 + am[i])*K + k0 + ak[i]);
            else    ra32[i] = *(const float4*)(Af + (long)(gm0 + am[i])*K + k0 + ak[i]);
        }
#pragma unroll
        for (int i = 0; i < BC; i++) {
            if (BH) rb16[i] = *(const uint4*)(Bhp + (long)(gn0 + bn[i])*K + k0 + bk[i]);
            else    rb32[i] = *(const float4*)(Bf + (long)(gn0 + bn[i])*K + k0 + bk[i]);
        }
    };
    auto sts = [&](int buf) {
#pragma unroll
        for (int i = 0; i < AC; i++) {
            if (AH) *(uint4*)&As[buf][am[i]][ak[i]] = ra16[i];
            else {
                __half2 lo = __floats2half2_rn(ra32[i].x, ra32[i].y);
                __half2 hi = __floats2half2_rn(ra32[i].z, ra32[i].w);
                *(__half2*)&As[buf][am[i]][ak[i]    ] = lo;
                *(__half2*)&As[buf][am[i]][ak[i] + 2] = hi;
            }
        }
#pragma unroll
        for (int i = 0; i < BC; i++) {
            if (BH) *(uint4*)&Bs[buf][bn[i]][bk[i]] = rb16[i];
            else {
                __half2 lo = __floats2half2_rn(rb32[i].x, rb32[i].y);
                __half2 hi = __floats2half2_rn(rb32[i].z, rb32[i].w);
                *(__half2*)&Bs[buf][bn[i]][bk[i]    ] = lo;
                *(__half2*)&Bs[buf][bn[i]][bk[i] + 2] = hi;
            }
        }
    };

    float acc[MT][NT][4];
#pragma unroll
    for (int i = 0; i < MT; i++)
#pragma unroll
        for (int j = 0; j < NT; j++)
#pragma unroll
            for (int q = 0; q < 4; q++) acc[i][j][q] = 0.0f;

    const int NI = K / BK;
    loadg(0);
    sts(0);
#pragma unroll 1
    for (int it = 0; it < NI; ++it) {
        __syncthreads();
        if (it + 1 < NI) loadg((it + 1) * BK);
        const int buf = it & 1;
        const uint32_t aB = buf * A_BUF, bB = buf * B_BUF;
#pragma unroll
        for (int ks = 0; ks < BK; ks += 16) {
            uint32_t af[MT][4], bq[NT/2][4];
#pragma unroll
            for (int i = 0; i < MT; i++) ldsm_x4(af[i], aAddr0[i] + aB + ks * 2);
#pragma unroll
            for (int jp = 0; jp < NT/2; jp++) ldsm_x4(bq[jp], bAddr0[jp] + bB + ks * 2);
#pragma unroll
            for (int i = 0; i < MT; i++)
#pragma unroll
                for (int j = 0; j < NT; j++)
                    mma_f16(acc[i][j], af[i][0], af[i][1], af[i][2], af[i][3],
                            bq[j >> 1][(j & 1) * 2], bq[j >> 1][(j & 1) * 2 + 1]);
        }
        if (it + 1 < NI) sts(buf ^ 1);
    }

#pragma unroll
    for (int i = 0; i < MT; i++) {
#pragma unroll
        for (int j = 0; j < NT; j++) {
#pragma unroll
            for (int h2 = 0; h2 < 2; h2++) {
                int m = gm0 + wm0 + i*16 + gid + h2*8;
                int n = gn0 + wn0 + j*8 + tg*2;
                float v0 = acc[i][j][h2*2 + 0];
                float v1 = acc[i][j][h2*2 + 1];
                if (bias) { v0 += bias[n]; v1 += bias[n+1]; }
                float sc = NORMROW ? rowinv[m] : scale;
                v0 *= sc; v1 *= sc;
                if (EPI == 0) {
                    if (CH) *(__half2*)(Chp + (long)m*ldc + n) = __floats2half2_rn(v0, v1);
                    else    *(float2*)(Cf + (long)m*ldc + n) = make_float2(v0, v1);
                } else if (EPI == 1) {
                    int h = n >> 6, d = n & 63;
                    *(__half2*)(Chp + (long)h*M*HD + (long)m*HD + d) =
                        __floats2half2_rn(v0, v1);
                } else {
                    int h = n >> 6, d = n & 63;
                    __half* p = Chp + (long)h*HD*M + (long)d*M + m;
                    p[0] = __float2half_rn(v0);
                    p[M] = __float2half_rn(v1);
                }
            }
        }
    }
}

// ---------------------------------------------------------------------------
__global__ __launch_bounds__(256) void cvt_k(const float* __restrict__ src,
                                             __half* __restrict__ dst)
{
    const long i = ((long)blockIdx.x * 256 + threadIdx.x) * 4;
    float4 t = *(const float4*)(src + i);
    __half2 lo = __floats2half2_rn(t.x, t.y);
    __half2 hi = __floats2half2_rn(t.z, t.w);
    *(__half2*)(dst + i)     = lo;
    *(__half2*)(dst + i + 2) = hi;
}

// ---------------------------------------------------------------------------
__global__ __launch_bounds__(256) void invred_k(const float* __restrict__ part,
                                                float* __restrict__ inv)
{
    const long row = (long)blockIdx.x * 256 + threadIdx.x;
    const float4 p = ((const float4*)part)[row];
    inv[row] = 1.0f / ((p.x + p.y) + (p.z + p.w));
}

// ---------------------------------------------------------------------------
__global__ __launch_bounds__(512) void avg_k(const __half* __restrict__ P,
                                             const float* __restrict__ inv,
                                             float* __restrict__ out)
{
    const int t = blockIdx.x, tid = threadIdx.x;
    const long TS = (long)T_LEN * T_LEN;
    const __half* base = P + (long)t * T_LEN + tid * 8;
    float acc[8];
#pragma unroll
    for (int q = 0; q < 8; q++) acc[q] = 0.f;
#pragma unroll
    for (int h = 0; h < H_NUM; h++) {
        const float iv = inv[h * T_LEN + t] * (1.0f / H_NUM);
        uint4 u = *(const uint4*)(base + (long)h * TS);
        float2 a = __half22float2(*(__half2*)&u.x);
        float2 b = __half22float2(*(__half2*)&u.y);
        float2 c = __half22float2(*(__half2*)&u.z);
        float2 d = __half22float2(*(__half2*)&u.w);
        acc[0] += a.x * iv; acc[1] += a.y * iv;
        acc[2] += b.x * iv; acc[3] += b.y * iv;
        acc[4] += c.x * iv; acc[5] += c.y * iv;
        acc[6] += d.x * iv; acc[7] += d.y * iv;
    }
    float* o = out + (long)t * T_LEN + tid * 8;
    *(float4*)(o)     = make_float4(acc[0], acc[1], acc[2], acc[3]);
    *(float4*)(o + 4) = make_float4(acc[4], acc[5], acc[6], acc[7]);
}

// ---------------------------------------------------------------------------
extern "C" void kernel_launch(void* const* d_in, const int* in_sizes, int n_in,
                              void* d_out, int out_size)
{
    const float* q_in = (const float*)d_in[0];
    const float* k_in = (const float*)d_in[1];
    const float* v_in = (const float*)d_in[2];
    const float* w    = (const float*)d_in[3];
    const float* b    = (const float*)d_in[4];
    const float* ow   = (const float*)d_in[5];
    const float* ob   = (const float*)d_in[6];
    float* out = (float*)d_out;

    __half *Q, *K, *Vt, *P, *CTX, *W16;
    float *RSP, *INV;
    cudaGetSymbolAddress((void**)&Q,   g_Q);
    cudaGetSymbolAddress((void**)&K,   g_K);
    cudaGetSymbolAddress((void**)&Vt,  g_Vt);
    cudaGetSymbolAddress((void**)&P,   g_P);
    cudaGetSymbolAddress((void**)&CTX, g_CTX);
    cudaGetSymbolAddress((void**)&W16, g_W16);
    cudaGetSymbolAddress((void**)&RSP, g_RSP);
    cudaGetSymbolAddress((void**)&INV, g_INV);

    const int T = T_LEN, E = E_DIM, H = H_NUM;
    const long EE = (long)E * E;
    dim3 blk(256);

    // weights -> fp16 (once per launch; deterministic)
    cvt_k<<<(int)(3*EE/4/256), 256>>>(w,  W16);
    cvt_k<<<(int)(EE/4/256),   256>>>(ow, W16 + 3*EE);

    // QKV projections: fp32 A, fp16 B -> fp16 head-major out
    gemm_k<128,128,2,4,1,false,true,false,true><<<dim3(E/128, T/128, 1), blk>>>(
        q_in, W16,        b,       Q,  nullptr, T, E, E, 0, 0,0,0,0, 0.125f);
    gemm_k<128,128,2,4,1,false,true,false,true><<<dim3(E/128, T/128, 1), blk>>>(
        k_in, W16 + EE,   b + E,   K,  nullptr, T, E, E, 0, 0,0,0,0, 1.0f);
    gemm_k<128,128,2,4,2,false,true,false,true><<<dim3(E/128, T/128, 1), blk>>>(
        v_in, W16 + 2*EE, b + 2*E, Vt, nullptr, T, E, E, 0, 0,0,0,0, 1.0f);

    // scores (3-stage pipeline) -> fp16 P + partial row sums
    scores_k<<<dim3(NBX_SCORES, T/128, H), blk>>>(Q, K, P, RSP);

    // row-sum reduce -> inv
    invred_k<<<(H*T)/256, 256>>>(RSP, INV);

    // head-average -> second half of d_out
    avg_k<<<T, 512>>>(P, INV, out + (long)T * E);

    // ctx: CTX[t, h*64+d] = inv[h][t] * (P16[h] @ Vt16[h]^T)
    gemm_k<128,64,4,2,0,true,true,true,true><<<dim3(1, T/128, H), blk>>>(
        P, Vt, nullptr, CTX, INV, T, HD, T, E,
        (long)T*T, (long)HD*T, 64, T, 1.0f);

    // out projection: fp16 CTX @ fp16 OW^T + bias -> fp32 out
    gemm_k<128,128,2,4,0,true,true,false,false><<<dim3(E/128, T/128, 1), blk>>>(
        CTX, W16 + 3*EE, ob, out, nullptr, T, E, E, E, 0,0,0,0, 1.0f);
}

// round 11
// speedup vs baseline: 1.2237x; 1.2237x over previous
#include <cuda_runtime.h>
#include <cuda_fp16.h>
#include <cstdint>

#define T_LEN 4096
#define E_DIM 1024
#define H_NUM 16
#define HD    64
#define NBX_SCORES 4     // column splits in scores kernel
#define NT_SC 8          // K-tiles per scores block

// Scratch (allocation-free rule: __device__ globals)
__device__ __half g_Q  [(long)H_NUM * T_LEN * HD];
__device__ __half g_K  [(long)H_NUM * T_LEN * HD];
__device__ __half g_Vt [(long)H_NUM * HD * T_LEN];
__device__ __half g_P  [(long)H_NUM * T_LEN * T_LEN];
__device__ __half g_CTX[(long)T_LEN * E_DIM];
__device__ float  g_RSP[(long)H_NUM * T_LEN * NBX_SCORES];
__device__ float  g_INV[(long)H_NUM * T_LEN];

__device__ __forceinline__ float ex2(float x) {
    float r;
    asm("ex2.approx.f32 %0, %1;" : "=f"(r) : "f"(x));
    return r;
}
__device__ __forceinline__ uint32_t smem_u32(const void* p) {
    return (uint32_t)__cvta_generic_to_shared(p);
}
__device__ __forceinline__ void ldsm_x4(uint32_t r[4], uint32_t addr) {
    asm volatile("ldmatrix.sync.aligned.m8n8.x4.shared.b16 {%0,%1,%2,%3}, [%4];"
        : "=r"(r[0]), "=r"(r[1]), "=r"(r[2]), "=r"(r[3]) : "r"(addr));
}
__device__ __forceinline__ void cp_async16(uint32_t saddr, const void* gaddr) {
    asm volatile("cp.async.cg.shared.global [%0], [%1], 16;" :: "r"(saddr), "l"(gaddr));
}
__device__ __forceinline__ void cp_commit() { asm volatile("cp.async.commit_group;"); }
template<int N>
__device__ __forceinline__ void cp_wait() {
    asm volatile("cp.async.wait_group %0;" :: "n"(N));
}

__device__ __forceinline__ void mma_f16(float c[4],
    uint32_t a0, uint32_t a1, uint32_t a2, uint32_t a3,
    uint32_t b0, uint32_t b1)
{
    asm volatile(
        "mma.sync.aligned.m16n8k16.row.col.f32.f16.f16.f32 "
        "{%0,%1,%2,%3}, {%4,%5,%6,%7}, {%8,%9}, {%0,%1,%2,%3};"
        : "+f"(c[0]), "+f"(c[1]), "+f"(c[2]), "+f"(c[3])
        : "r"(a0), "r"(a1), "r"(a2), "r"(a3), "r"(b0), "r"(b1));
}

#define LOG2E 1.4426950408889634f
#define PSHIFT 2.0f

// ===========================================================================
// Scores (R9 version, unchanged): 2-stage cp.async, Q frags in registers.
// ===========================================================================
__global__ __launch_bounds__(256, 2)
void scores_k(const __half* __restrict__ Q, const __half* __restrict__ Kp,
              __half* __restrict__ P, float* __restrict__ rsp)
{
    __shared__ __half Qs[128][72];
    __shared__ __half Ks[2][128][72];
    __shared__ float  srs[512];

    const int tid  = threadIdx.x;
    const int warp = tid >> 5, lane = tid & 31;
    const int gid = lane >> 2, tg = lane & 3;
    const int wm0 = (warp >> 2) * 64;
    const int wn0 = (warp & 3) * 32;
    const int gm0 = blockIdx.y * 128;
    const int cbase = blockIdx.x * (NT_SC * 128);

    const __half* Ah = Q  + (long)blockIdx.z * T_LEN * HD + (long)gm0 * HD;
    const __half* Kh = Kp + (long)blockIdx.z * T_LEN * HD + (long)cbase * HD;

    int lm[4], lk[4];
#pragma unroll
    for (int i = 0; i < 4; i++) {
        const int idx = (tid + i * 256) * 8;
        lm[i] = idx >> 6; lk[i] = idx & 63;
    }
    auto prefetchK = [&](int nt, int buf) {
#pragma unroll
        for (int i = 0; i < 4; i++)
            cp_async16(smem_u32(&Ks[buf][lm[i]][lk[i]]),
                       Kh + ((long)nt * 128 + lm[i]) * HD + lk[i]);
    };

#pragma unroll
    for (int i = 0; i < 4; i++)
        cp_async16(smem_u32(&Qs[lm[i]][lk[i]]), Ah + (long)lm[i] * HD + lk[i]);
    prefetchK(0, 0); cp_commit();
    prefetchK(1, 1); cp_commit();
    cp_wait<1>();
    __syncthreads();

    uint32_t af[4][4][4];
#pragma unroll
    for (int i = 0; i < 4; i++) {
        const uint32_t a = smem_u32(&Qs[wm0 + i*16 + (lane & 15)][(lane >> 4) * 8]);
#pragma unroll
        for (int ks = 0; ks < 4; ks++) ldsm_x4(af[ks][i], a + ks * 32);
    }

    uint32_t bAddr[2][2];
#pragma unroll
    for (int buf = 0; buf < 2; buf++)
#pragma unroll
        for (int jp = 0; jp < 2; jp++)
            bAddr[buf][jp] = smem_u32(
                &Ks[buf][wn0 + jp*16 + (lane & 7) + ((lane >> 4) << 3)]
                        [((lane >> 3) & 1) * 8]);

    float rsum[4][2];
#pragma unroll
    for (int i = 0; i < 4; i++) { rsum[i][0] = 0.f; rsum[i][1] = 0.f; }

    __half* Ch = P + (long)blockIdx.z * T_LEN * T_LEN;

#pragma unroll 1
    for (int nt = 0; nt < NT_SC; nt++) {
        const int buf = nt & 1;

        float acc[4][4][4];
#pragma unroll
        for (int i = 0; i < 4; i++)
#pragma unroll
            for (int j = 0; j < 4; j++)
#pragma unroll
                for (int q = 0; q < 4; q++) acc[i][j][q] = 0.0f;

#pragma unroll
        for (int ks = 0; ks < 4; ks++) {
            uint32_t bq[2][4];
#pragma unroll
            for (int jp = 0; jp < 2; jp++)
                ldsm_x4(bq[jp], bAddr[buf][jp] + ks * 32);
#pragma unroll
            for (int i = 0; i < 4; i++)
#pragma unroll
                for (int j = 0; j < 4; j++)
                    mma_f16(acc[i][j], af[ks][i][0], af[ks][i][1],
                            af[ks][i][2], af[ks][i][3],
                            bq[j >> 1][(j & 1) * 2], bq[j >> 1][(j & 1) * 2 + 1]);
        }

        const int n0t = cbase + nt * 128;
#pragma unroll
        for (int i = 0; i < 4; i++) {
#pragma unroll
            for (int j = 0; j < 4; j++) {
#pragma unroll
                for (int h2 = 0; h2 < 2; h2++) {
                    const int m = gm0 + wm0 + i * 16 + gid + h2 * 8;
                    const int n = n0t + wn0 + j * 8 + tg * 2;
                    float v0 = ex2(fmaf(acc[i][j][h2 * 2 + 0], LOG2E, PSHIFT));
                    float v1 = ex2(fmaf(acc[i][j][h2 * 2 + 1], LOG2E, PSHIFT));
                    rsum[i][h2] += v0 + v1;
                    *(__half2*)(Ch + (long)m * T_LEN + n) = __floats2half2_rn(v0, v1);
                }
            }
        }

        __syncthreads();
        if (nt + 2 < NT_SC) { prefetchK(nt + 2, buf); cp_commit(); }
        if (nt + 1 < NT_SC) {
            if (nt + 2 < NT_SC) cp_wait<1>(); else cp_wait<0>();
            __syncthreads();
        }
    }

#pragma unroll
    for (int i = 0; i < 4; i++)
#pragma unroll
        for (int h2 = 0; h2 < 2; h2++)
#pragma unroll
            for (int o = 1; o < 4; o <<= 1)
                rsum[i][h2] += __shfl_xor_sync(0xffffffffu, rsum[i][h2], o);
    if (tg == 0) {
        const int wn = warp & 3;
#pragma unroll
        for (int i = 0; i < 4; i++)
#pragma unroll
            for (int h2 = 0; h2 < 2; h2++)
                srs[wn * 128 + wm0 + i * 16 + h2 * 8 + gid] = rsum[i][h2];
    }
    __syncthreads();
    if (tid < 128) {
        float s = srs[tid] + srs[128 + tid] + srs[256 + tid] + srs[384 + tid];
        rsp[((long)blockIdx.z * T_LEN + gm0 + tid) * NBX_SCORES + blockIdx.x] = s;
    }
}

// ===========================================================================
// Dedicated ctx kernel: CTX[t, h*64+d] = inv[h][t] * (P16[h] @ Vt16[h]^T)
// grid (T/128, H), 256 thr, 8 warps (4x2), warp tile 32x32.
// 3-stage cp.async pipeline over s-chunks of 64 (P tile 128x64, Vt tile 64x64).
// ===========================================================================
#define CTX_BK 64
#define CTX_NI (T_LEN / CTX_BK)   // 64

__global__ __launch_bounds__(256, 2)
void ctx_k(const __half* __restrict__ P, const __half* __restrict__ Vt,
           const float* __restrict__ inv, __half* __restrict__ CTX)
{
    __shared__ __half Ps[3][128][72];
    __shared__ __half Vs[3][64][72];

    const int tid  = threadIdx.x;
    const int warp = tid >> 5, lane = tid & 31;
    const int gid = lane >> 2, tg = lane & 3;
    const int wm0 = (warp >> 1) * 32;    // 4 warps in M
    const int wn0 = (warp & 1) * 32;     // 2 warps in N
    const int gm0 = blockIdx.x * 128;
    const int h   = blockIdx.y;

    const __half* Ph = P  + (long)h * T_LEN * T_LEN + (long)gm0 * T_LEN;
    const __half* Vh = Vt + (long)h * HD * T_LEN;

    // load indices: A 128x64 halfs = 1024 uint4 -> 4/thread; B 64x64 -> 2/thread
    int am[4], ak[4], bd[2], bk[2];
#pragma unroll
    for (int i = 0; i < 4; i++) {
        const int idx = (tid + i * 256) * 8;
        am[i] = idx >> 6; ak[i] = idx & 63;
    }
#pragma unroll
    for (int i = 0; i < 2; i++) {
        const int idx = (tid + i * 256) * 8;
        bd[i] = idx >> 6; bk[i] = idx & 63;
    }

    auto prefetch = [&](int it, int buf) {
        const int s0 = it * CTX_BK;
#pragma unroll
        for (int i = 0; i < 4; i++)
            cp_async16(smem_u32(&Ps[buf][am[i]][ak[i]]),
                       Ph + (long)am[i] * T_LEN + s0 + ak[i]);
#pragma unroll
        for (int i = 0; i < 2; i++)
            cp_async16(smem_u32(&Vs[buf][bd[i]][bk[i]]),
                       Vh + (long)bd[i] * T_LEN + s0 + bk[i]);
    };

    prefetch(0, 0); cp_commit();
    prefetch(1, 1); cp_commit();
    prefetch(2, 2); cp_commit();
    cp_wait<2>();
    __syncthreads();

    // LDSM base addresses per stage
    uint32_t aAddr[3][2], bAddr[3][2];
#pragma unroll
    for (int st = 0; st < 3; st++) {
#pragma unroll
        for (int i = 0; i < 2; i++)
            aAddr[st][i] = smem_u32(
                &Ps[st][wm0 + i*16 + (lane & 15)][(lane >> 4) * 8]);
#pragma unroll
        for (int jp = 0; jp < 2; jp++)
            bAddr[st][jp] = smem_u32(
                &Vs[st][wn0 + jp*16 + (lane & 7) + ((lane >> 4) << 3)]
                       [((lane >> 3) & 1) * 8]);
    }

    float acc[2][4][4];
#pragma unroll
    for (int i = 0; i < 2; i++)
#pragma unroll
        for (int j = 0; j < 4; j++)
#pragma unroll
            for (int q = 0; q < 4; q++) acc[i][j][q] = 0.0f;

#pragma unroll 1
    for (int it = 0; it < CTX_NI; ++it) {
        const int buf = it % 3;
#pragma unroll
        for (int ks = 0; ks < 4; ks++) {
            uint32_t af[2][4], bq[2][4];
#pragma unroll
            for (int i = 0; i < 2; i++) ldsm_x4(af[i], aAddr[buf][i] + ks * 32);
#pragma unroll
            for (int jp = 0; jp < 2; jp++) ldsm_x4(bq[jp], bAddr[buf][jp] + ks * 32);
#pragma unroll
            for (int i = 0; i < 2; i++)
#pragma unroll
                for (int j = 0; j < 4; j++)
                    mma_f16(acc[i][j], af[i][0], af[i][1], af[i][2], af[i][3],
                            bq[j >> 1][(j & 1) * 2], bq[j >> 1][(j & 1) * 2 + 1]);
        }
        __syncthreads();                         // done reading buf
        if (it + 3 < CTX_NI) { prefetch(it + 3, buf); cp_commit(); }
        if (it + 1 < CTX_NI) {
            if (it + 3 < CTX_NI)       cp_wait<2>();
            else if (it + 2 < CTX_NI)  cp_wait<1>();
            else                       cp_wait<0>();
            __syncthreads();
        }
    }

    // epilogue: scale rows by inv[h][m], store fp16 CTX
    const float* invh = inv + (long)h * T_LEN;
#pragma unroll
    for (int i = 0; i < 2; i++) {
#pragma unroll
        for (int j = 0; j < 4; j++) {
#pragma unroll
            for (int h2 = 0; h2 < 2; h2++) {
                const int m = gm0 + wm0 + i*16 + gid + h2*8;
                const int n = h * HD + wn0 + j*8 + tg*2;
                const float sc = invh[m];
                float v0 = acc[i][j][h2*2 + 0] * sc;
                float v1 = acc[i][j][h2*2 + 1] * sc;
                *(__half2*)(CTX + (long)m * E_DIM + n) = __floats2half2_rn(v0, v1);
            }
        }
    }
}

// ===========================================================================
// Generic fp16-MMA GEMM (R9 version) — projections + out-projection.
// ===========================================================================
template<int BM, int BN, int WARPS_M, int WARPS_N,
         int EPI, bool AH, bool BH, bool NORMROW, bool CH>
__global__ __launch_bounds__(WARPS_M*WARPS_N*32)
void gemm_k(const void* __restrict__ Av, const void* __restrict__ Bv,
            const float* __restrict__ bias, void* __restrict__ Cv,
            const float* __restrict__ rowinv,
            int M, int N, int K, int ldc,
            long aH, long bH, long cH, long riH, float scale)
{
    constexpr int THREADS = WARPS_M*WARPS_N*32;
    constexpr int BK = 32;
    constexpr int WM = BM/WARPS_M, WN = BN/WARPS_N;
    constexpr int MT = WM/16, NT = WN/8;
    static_assert(NT % 2 == 0, "NT must be even");

    const float*  Af  = (const float*) Av + (AH ? 0 : blockIdx.z * aH);
    const __half* Ahp = (const __half*)Av + (AH ? blockIdx.z * aH : 0);
    const float*  Bf  = (const float*) Bv + (BH ? 0 : blockIdx.z * bH);
    const __half* Bhp = (const __half*)Bv + (BH ? blockIdx.z * bH : 0);
    float*  Cf  = (float*) Cv + (CH ? 0 : blockIdx.z * cH);
    __half* Chp = (__half*)Cv + (CH ? blockIdx.z * cH : 0);
    if (NORMROW) rowinv += blockIdx.z * riH;

    __shared__ __half As[2][BM][40];
    __shared__ __half Bs[2][BN][40];

    const int tid  = threadIdx.x;
    const int warp = tid >> 5, lane = tid & 31;
    const int wm0 = (warp / WARPS_N) * WM;
    const int wn0 = (warp % WARPS_N) * WN;
    const int gid = lane >> 2, tg = lane & 3;
    const int gm0 = blockIdx.y * BM, gn0 = blockIdx.x * BN;

    constexpr int AC = AH ? BM*BK/(THREADS*8) : BM*BK/(THREADS*4);
    constexpr int BC = BH ? BN*BK/(THREADS*8) : BN*BK/(THREADS*4);
    int am[AC], ak[AC], bn[BC], bk[BC];
#pragma unroll
    for (int i = 0; i < AC; i++) {
        int idx = (tid + i*THREADS) * (AH ? 8 : 4);
        am[i] = idx / BK; ak[i] = idx % BK;
    }
#pragma unroll
    for (int i = 0; i < BC; i++) {
        int idx = (tid + i*THREADS) * (BH ? 8 : 4);
        bn[i] = idx / BK; bk[i] = idx % BK;
    }

    constexpr uint32_t A_BUF = BM * 40 * 2;
    constexpr uint32_t B_BUF = BN * 40 * 2;
    uint32_t aAddr0[MT], bAddr0[NT/2];
#pragma unroll
    for (int i = 0; i < MT; i++)
        aAddr0[i] = smem_u32(&As[0][wm0 + i*16 + (lane & 15)][(lane >> 4) * 8]);
#pragma unroll
    for (int jp = 0; jp < NT/2; jp++)
        bAddr0[jp] = smem_u32(&Bs[0][wn0 + jp*16 + (lane & 7) + ((lane >> 4) << 3)]
                                 [((lane >> 3) & 1) * 8]);

    uint4  ra16[AC], rb16[BC];
    float4 ra32[AC], rb32[BC];
    auto loadg = [&](int k0) {
#pragma unroll
        for (int i = 0; i < AC; i++) {
            if (AH) ra16[i] = *(const uint4*)(Ahp + (long)(gm0 + am[i])*K + k0 + ak[i]);
            else    ra32[i] = *(const float4*)(Af + (long)(gm0 + am[i])*K + k0 + ak[i]);
        }
#pragma unroll
        for (int i = 0; i < BC; i++) {
            if (BH) rb16[i] = *(const uint4*)(Bhp + (long)(gn0 + bn[i])*K + k0 + bk[i]);
            else    rb32[i] = *(const float4*)(Bf + (long)(gn0 + bn[i])*K + k0 + bk[i]);
        }
    };
    auto sts = [&](int buf) {
#pragma unroll
        for (int i = 0; i < AC; i++) {
            if (AH) *(uint4*)&As[buf][am[i]][ak[i]] = ra16[i];
            else {
                __half2 lo = __floats2half2_rn(ra32[i].x, ra32[i].y);
                __half2 hi = __floats2half2_rn(ra32[i].z, ra32[i].w);
                *(__half2*)&As[buf][am[i]][ak[i]    ] = lo;
                *(__half2*)&As[buf][am[i]][ak[i] + 2] = hi;
            }
        }
#pragma unroll
        for (int i = 0; i < BC; i++) {
            if (BH) *(uint4*)&Bs[buf][bn[i]][bk[i]] = rb16[i];
            else {
                __half2 lo = __floats2half2_rn(rb32[i].x, rb32[i].y);
                __half2 hi = __floats2half2_rn(rb32[i].z, rb32[i].w);
                *(__half2*)&Bs[buf][bn[i]][bk[i]    ] = lo;
                *(__half2*)&Bs[buf][bn[i]][bk[i] + 2] = hi;
            }
        }
    };

    float acc[MT][NT][4];
#pragma unroll
    for (int i = 0; i < MT; i++)
#pragma unroll
        for (int j = 0; j < NT; j++)
#pragma unroll
            for (int q = 0; q < 4; q++) acc[i][j][q] = 0.0f;

    const int NI = K / BK;
    loadg(0);
    sts(0);
#pragma unroll 1
    for (int it = 0; it < NI; ++it) {
        __syncthreads();
        if (it + 1 < NI) loadg((it + 1) * BK);
        const int buf = it & 1;
        const uint32_t aB = buf * A_BUF, bB = buf * B_BUF;
#pragma unroll
        for (int ks = 0; ks < BK; ks += 16) {
            uint32_t af[MT][4], bq[NT/2][4];
#pragma unroll
            for (int i = 0; i < MT; i++) ldsm_x4(af[i], aAddr0[i] + aB + ks * 2);
#pragma unroll
            for (int jp = 0; jp < NT/2; jp++) ldsm_x4(bq[jp], bAddr0[jp] + bB + ks * 2);
#pragma unroll
            for (int i = 0; i < MT; i++)
#pragma unroll
                for (int j = 0; j < NT; j++)
                    mma_f16(acc[i][j], af[i][0], af[i][1], af[i][2], af[i][3],
                            bq[j >> 1][(j & 1) * 2], bq[j >> 1][(j & 1) * 2 + 1]);
        }
        if (it + 1 < NI) sts(buf ^ 1);
    }

#pragma unroll
    for (int i = 0; i < MT; i++) {
#pragma unroll
        for (int j = 0; j < NT; j++) {
#pragma unroll
            for (int h2 = 0; h2 < 2; h2++) {
                int m = gm0 + wm0 + i*16 + gid + h2*8;
                int n = gn0 + wn0 + j*8 + tg*2;
                float v0 = acc[i][j][h2*2 + 0];
                float v1 = acc[i][j][h2*2 + 1];
                if (bias) { v0 += bias[n]; v1 += bias[n+1]; }
                float sc = NORMROW ? rowinv[m] : scale;
                v0 *= sc; v1 *= sc;
                if (EPI == 0) {
                    if (CH) *(__half2*)(Chp + (long)m*ldc + n) = __floats2half2_rn(v0, v1);
                    else    *(float2*)(Cf + (long)m*ldc + n) = make_float2(v0, v1);
                } else if (EPI == 1) {
                    int h = n >> 6, d = n & 63;
                    *(__half2*)(Chp + (long)h*M*HD + (long)m*HD + d) =
                        __floats2half2_rn(v0, v1);
                } else {
                    int h = n >> 6, d = n & 63;
                    __half* p = Chp + (long)h*HD*M + (long)d*M + m;
                    p[0] = __float2half_rn(v0);
                    p[M] = __float2half_rn(v1);
                }
            }
        }
    }
}

// ---------------------------------------------------------------------------
__global__ __launch_bounds__(256) void invred_k(const float* __restrict__ part,
                                                float* __restrict__ inv)
{
    const long row = (long)blockIdx.x * 256 + threadIdx.x;
    const float4 p = ((const float4*)part)[row];
    inv[row] = 1.0f / ((p.x + p.y) + (p.z + p.w));
}

// ---------------------------------------------------------------------------
__global__ __launch_bounds__(1024) void avg_k(const __half* __restrict__ P,
                                              const float* __restrict__ inv,
                                              float* __restrict__ out)
{
    const int t = blockIdx.x, tid = threadIdx.x;
    const long TS = (long)T_LEN * T_LEN;
    const __half* base = P + (long)t * T_LEN + tid * 4;
    float4 acc = make_float4(0.f, 0.f, 0.f, 0.f);
#pragma unroll
    for (int h = 0; h < H_NUM; h++) {
        const float iv = inv[h * T_LEN + t] * (1.0f / H_NUM);
        uint2 u = *(const uint2*)(base + (long)h * TS);
        float2 lo = __half22float2(*(__half2*)&u.x);
        float2 hi = __half22float2(*(__half2*)&u.y);
        acc.x += lo.x * iv; acc.y += lo.y * iv;
        acc.z += hi.x * iv; acc.w += hi.y * iv;
    }
    ((float4*)(out + (long)t * T_LEN))[tid] = acc;
}

// ---------------------------------------------------------------------------
extern "C" void kernel_launch(void* const* d_in, const int* in_sizes, int n_in,
                              void* d_out, int out_size)
{
    const float* q_in = (const float*)d_in[0];
    const float* k_in = (const float*)d_in[1];
    const float* v_in = (const float*)d_in[2];
    const float* w    = (const float*)d_in[3];
    const float* b    = (const float*)d_in[4];
    const float* ow   = (const float*)d_in[5];
    const float* ob   = (const float*)d_in[6];
    float* out = (float*)d_out;

    __half *Q, *K, *Vt, *P, *CTX;
    float *RSP, *INV;
    cudaGetSymbolAddress((void**)&Q,   g_Q);
    cudaGetSymbolAddress((void**)&K,   g_K);
    cudaGetSymbolAddress((void**)&Vt,  g_Vt);
    cudaGetSymbolAddress((void**)&P,   g_P);
    cudaGetSymbolAddress((void**)&CTX, g_CTX);
    cudaGetSymbolAddress((void**)&RSP, g_RSP);
    cudaGetSymbolAddress((void**)&INV, g_INV);

    const int T = T_LEN, E = E_DIM, H = H_NUM;
    const long EE = (long)E * E;
    dim3 blk(256);

    // QKV projections: fp32 in -> fp16 head-major out
    gemm_k<128,128,2,4,1,false,false,false,true><<<dim3(E/128, T/128, 1), blk>>>(
        q_in, w,        b,       Q,  nullptr, T, E, E, 0, 0,0,0,0, 0.125f);
    gemm_k<128,128,2,4,1,false,false,false,true><<<dim3(E/128, T/128, 1), blk>>>(
        k_in, w + EE,   b + E,   K,  nullptr, T, E, E, 0, 0,0,0,0, 1.0f);
    gemm_k<128,128,2,4,2,false,false,false,true><<<dim3(E/128, T/128, 1), blk>>>(
        v_in, w + 2*EE, b + 2*E, Vt, nullptr, T, E, E, 0, 0,0,0,0, 1.0f);

    // scores (pipelined) -> fp16 P + partial row sums
    scores_k<<<dim3(NBX_SCORES, T/128, H), blk>>>(Q, K, P, RSP);

    // row-sum reduce -> inv
    invred_k<<<(H*T)/256, 256>>>(RSP, INV);

    // head-average -> second half of d_out
    avg_k<<<T, 1024>>>(P, INV, out + (long)T * E);

    // ctx (dedicated pipelined kernel)
    ctx_k<<<dim3(T/128, H), blk>>>(P, Vt, INV, CTX);

    // out projection: fp16 CTX @ fp32 W^T + bias -> fp32 out
    gemm_k<128,128,2,4,0,true,false,false,false><<<dim3(E/128, T/128, 1), blk>>>(
        CTX, ow, ob, out, nullptr, T, E, E, E, 0,0,0,0, 1.0f);
}

// round 12
// speedup vs baseline: 1.2630x; 1.0321x over previous
#include <cuda_runtime.h>
#include <cuda_fp16.h>
#include <cstdint>

#define T_LEN 4096
#define E_DIM 1024
#define H_NUM 16
#define HD    64
#define NBX_SCORES 4     // column splits in scores kernel
#define NT_SC 8          // K-tiles per scores block

// Scratch (allocation-free rule: __device__ globals)
__device__ __half g_Q  [(long)H_NUM * T_LEN * HD];
__device__ __half g_K  [(long)H_NUM * T_LEN * HD];
__device__ __half g_Vt [(long)H_NUM * HD * T_LEN];
__device__ __half g_P  [(long)H_NUM * T_LEN * T_LEN];
__device__ __half g_CTX[(long)T_LEN * E_DIM];
__device__ float  g_RSP[(long)H_NUM * T_LEN * NBX_SCORES];
__device__ float  g_INV[(long)H_NUM * T_LEN];

__device__ __forceinline__ float ex2(float x) {
    float r;
    asm("ex2.approx.f32 %0, %1;" : "=f"(r) : "f"(x));
    return r;
}
__device__ __forceinline__ uint32_t smem_u32(const void* p) {
    return (uint32_t)__cvta_generic_to_shared(p);
}
__device__ __forceinline__ void ldsm_x4(uint32_t r[4], uint32_t addr) {
    asm volatile("ldmatrix.sync.aligned.m8n8.x4.shared.b16 {%0,%1,%2,%3}, [%4];"
        : "=r"(r[0]), "=r"(r[1]), "=r"(r[2]), "=r"(r[3]) : "r"(addr));
}
__device__ __forceinline__ void cp_async16(uint32_t saddr, const void* gaddr) {
    asm volatile("cp.async.cg.shared.global [%0], [%1], 16;" :: "r"(saddr), "l"(gaddr));
}
__device__ __forceinline__ void cp_commit() { asm volatile("cp.async.commit_group;"); }
template<int N>
__device__ __forceinline__ void cp_wait() {
    asm volatile("cp.async.wait_group %0;" :: "n"(N));
}

__device__ __forceinline__ void mma_f16(float c[4],
    uint32_t a0, uint32_t a1, uint32_t a2, uint32_t a3,
    uint32_t b0, uint32_t b1)
{
    asm volatile(
        "mma.sync.aligned.m16n8k16.row.col.f32.f16.f16.f32 "
        "{%0,%1,%2,%3}, {%4,%5,%6,%7}, {%8,%9}, {%0,%1,%2,%3};"
        : "+f"(c[0]), "+f"(c[1]), "+f"(c[2]), "+f"(c[3])
        : "r"(a0), "r"(a1), "r"(a2), "r"(a3), "r"(b0), "r"(b1));
}

#define LOG2E 1.4426950408889634f
#define PSHIFT 2.0f

// ===========================================================================
// Scores: 2-stage cp.async (R11 structure), Q frags register-resident,
// epilogue uses quad-transpose + STG.128 (the single change this round).
// ===========================================================================
__global__ __launch_bounds__(256, 2)
void scores_k(const __half* __restrict__ Q, const __half* __restrict__ Kp,
              __half* __restrict__ P, float* __restrict__ rsp)
{
    __shared__ __half Qs[128][72];
    __shared__ __half Ks[2][128][72];
    __shared__ float  srs[512];

    const int tid  = threadIdx.x;
    const int warp = tid >> 5, lane = tid & 31;
    const int gid = lane >> 2, tg = lane & 3;
    const int wm0 = (warp >> 2) * 64;
    const int wn0 = (warp & 3) * 32;
    const int gm0 = blockIdx.y * 128;
    const int cbase = blockIdx.x * (NT_SC * 128);

    const __half* Ah = Q  + (long)blockIdx.z * T_LEN * HD + (long)gm0 * HD;
    const __half* Kh = Kp + (long)blockIdx.z * T_LEN * HD + (long)cbase * HD;

    int lm[4], lk[4];
#pragma unroll
    for (int i = 0; i < 4; i++) {
        const int idx = (tid + i * 256) * 8;
        lm[i] = idx >> 6; lk[i] = idx & 63;
    }
    auto prefetchK = [&](int nt, int buf) {
#pragma unroll
        for (int i = 0; i < 4; i++)
            cp_async16(smem_u32(&Ks[buf][lm[i]][lk[i]]),
                       Kh + ((long)nt * 128 + lm[i]) * HD + lk[i]);
    };

#pragma unroll
    for (int i = 0; i < 4; i++)
        cp_async16(smem_u32(&Qs[lm[i]][lk[i]]), Ah + (long)lm[i] * HD + lk[i]);
    prefetchK(0, 0); cp_commit();
    prefetchK(1, 1); cp_commit();
    cp_wait<1>();
    __syncthreads();

    uint32_t af[4][4][4];
#pragma unroll
    for (int i = 0; i < 4; i++) {
        const uint32_t a = smem_u32(&Qs[wm0 + i*16 + (lane & 15)][(lane >> 4) * 8]);
#pragma unroll
        for (int ks = 0; ks < 4; ks++) ldsm_x4(af[ks][i], a + ks * 32);
    }

    uint32_t bAddr[2][2];
#pragma unroll
    for (int buf = 0; buf < 2; buf++)
#pragma unroll
        for (int jp = 0; jp < 2; jp++)
            bAddr[buf][jp] = smem_u32(
                &Ks[buf][wn0 + jp*16 + (lane & 7) + ((lane >> 4) << 3)]
                        [((lane >> 3) & 1) * 8]);

    float rsum[4][2];
#pragma unroll
    for (int i = 0; i < 4; i++) { rsum[i][0] = 0.f; rsum[i][1] = 0.f; }

    __half* Ch = P + (long)blockIdx.z * T_LEN * T_LEN;

#pragma unroll 1
    for (int nt = 0; nt < NT_SC; nt++) {
        const int buf = nt & 1;

        float acc[4][4][4];
#pragma unroll
        for (int i = 0; i < 4; i++)
#pragma unroll
            for (int j = 0; j < 4; j++)
#pragma unroll
                for (int q = 0; q < 4; q++) acc[i][j][q] = 0.0f;

#pragma unroll
        for (int ks = 0; ks < 4; ks++) {
            uint32_t bq[2][4];
#pragma unroll
            for (int jp = 0; jp < 2; jp++)
                ldsm_x4(bq[jp], bAddr[buf][jp] + ks * 32);
#pragma unroll
            for (int i = 0; i < 4; i++)
#pragma unroll
                for (int j = 0; j < 4; j++)
                    mma_f16(acc[i][j], af[ks][i][0], af[ks][i][1],
                            af[ks][i][2], af[ks][i][3],
                            bq[j >> 1][(j & 1) * 2], bq[j >> 1][(j & 1) * 2 + 1]);
        }

        // epilogue: exp -> quad transpose -> STG.128
        const int n0t = cbase + nt * 128;
#pragma unroll
        for (int i = 0; i < 4; i++) {
#pragma unroll
            for (int h2 = 0; h2 < 2; h2++) {
                uint32_t hp[4];
#pragma unroll
                for (int j = 0; j < 4; j++) {
                    float v0 = ex2(fmaf(acc[i][j][h2*2 + 0], LOG2E, PSHIFT));
                    float v1 = ex2(fmaf(acc[i][j][h2*2 + 1], LOG2E, PSHIFT));
                    rsum[i][h2] += v0 + v1;
                    __half2 h = __floats2half2_rn(v0, v1);
                    hp[j] = *(uint32_t*)&h;
                }
                // 4x4 transpose across quad lanes (xor 1 then xor 2)
                {
                    uint32_t t, r;
                    t = (tg & 1) ? hp[0] : hp[1];
                    r = __shfl_xor_sync(0xffffffffu, t, 1);
                    if (tg & 1) hp[0] = r; else hp[1] = r;
                    t = (tg & 1) ? hp[2] : hp[3];
                    r = __shfl_xor_sync(0xffffffffu, t, 1);
                    if (tg & 1) hp[2] = r; else hp[3] = r;
                    t = (tg & 2) ? hp[0] : hp[2];
                    r = __shfl_xor_sync(0xffffffffu, t, 2);
                    if (tg & 2) hp[0] = r; else hp[2] = r;
                    t = (tg & 2) ? hp[1] : hp[3];
                    r = __shfl_xor_sync(0xffffffffu, t, 2);
                    if (tg & 2) hp[1] = r; else hp[3] = r;
                }
                const int m = gm0 + wm0 + i * 16 + gid + h2 * 8;
                const int n = n0t + wn0 + tg * 8;
                *(uint4*)(Ch + (long)m * T_LEN + n) =
                    make_uint4(hp[0], hp[1], hp[2], hp[3]);
            }
        }

        __syncthreads();
        if (nt + 2 < NT_SC) { prefetchK(nt + 2, buf); cp_commit(); }
        if (nt + 1 < NT_SC) {
            if (nt + 2 < NT_SC) cp_wait<1>(); else cp_wait<0>();
            __syncthreads();
        }
    }

#pragma unroll
    for (int i = 0; i < 4; i++)
#pragma unroll
        for (int h2 = 0; h2 < 2; h2++)
#pragma unroll
            for (int o = 1; o < 4; o <<= 1)
                rsum[i][h2] += __shfl_xor_sync(0xffffffffu, rsum[i][h2], o);
    if (tg == 0) {
        const int wn = warp & 3;
#pragma unroll
        for (int i = 0; i < 4; i++)
#pragma unroll
            for (int h2 = 0; h2 < 2; h2++)
                srs[wn * 128 + wm0 + i * 16 + h2 * 8 + gid] = rsum[i][h2];
    }
    __syncthreads();
    if (tid < 128) {
        float s = srs[tid] + srs[128 + tid] + srs[256 + tid] + srs[384 + tid];
        rsp[((long)blockIdx.z * T_LEN + gm0 + tid) * NBX_SCORES + blockIdx.x] = s;
    }
}

// ===========================================================================
// Dedicated ctx kernel (R11, unchanged).
// ===========================================================================
#define CTX_BK 64
#define CTX_NI (T_LEN / CTX_BK)   // 64

__global__ __launch_bounds__(256, 2)
void ctx_k(const __half* __restrict__ P, const __half* __restrict__ Vt,
           const float* __restrict__ inv, __half* __restrict__ CTX)
{
    __shared__ __half Ps[3][128][72];
    __shared__ __half Vs[3][64][72];

    const int tid  = threadIdx.x;
    const int warp = tid >> 5, lane = tid & 31;
    const int gid = lane >> 2, tg = lane & 3;
    const int wm0 = (warp >> 1) * 32;
    const int wn0 = (warp & 1) * 32;
    const int gm0 = blockIdx.x * 128;
    const int h   = blockIdx.y;

    const __half* Ph = P  + (long)h * T_LEN * T_LEN + (long)gm0 * T_LEN;
    const __half* Vh = Vt + (long)h * HD * T_LEN;

    int am[4], ak[4], bd[2], bk[2];
#pragma unroll
    for (int i = 0; i < 4; i++) {
        const int idx = (tid + i * 256) * 8;
        am[i] = idx >> 6; ak[i] = idx & 63;
    }
#pragma unroll
    for (int i = 0; i < 2; i++) {
        const int idx = (tid + i * 256) * 8;
        bd[i] = idx >> 6; bk[i] = idx & 63;
    }

    auto prefetch = [&](int it, int buf) {
        const int s0 = it * CTX_BK;
#pragma unroll
        for (int i = 0; i < 4; i++)
            cp_async16(smem_u32(&Ps[buf][am[i]][ak[i]]),
                       Ph + (long)am[i] * T_LEN + s0 + ak[i]);
#pragma unroll
        for (int i = 0; i < 2; i++)
            cp_async16(smem_u32(&Vs[buf][bd[i]][bk[i]]),
                       Vh + (long)bd[i] * T_LEN + s0 + bk[i]);
    };

    prefetch(0, 0); cp_commit();
    prefetch(1, 1); cp_commit();
    prefetch(2, 2); cp_commit();
    cp_wait<2>();
    __syncthreads();

    uint32_t aAddr[3][2], bAddr[3][2];
#pragma unroll
    for (int st = 0; st < 3; st++) {
#pragma unroll
        for (int i = 0; i < 2; i++)
            aAddr[st][i] = smem_u32(
                &Ps[st][wm0 + i*16 + (lane & 15)][(lane >> 4) * 8]);
#pragma unroll
        for (int jp = 0; jp < 2; jp++)
            bAddr[st][jp] = smem_u32(
                &Vs[st][wn0 + jp*16 + (lane & 7) + ((lane >> 4) << 3)]
                       [((lane >> 3) & 1) * 8]);
    }

    float acc[2][4][4];
#pragma unroll
    for (int i = 0; i < 2; i++)
#pragma unroll
        for (int j = 0; j < 4; j++)
#pragma unroll
            for (int q = 0; q < 4; q++) acc[i][j][q] = 0.0f;

#pragma unroll 1
    for (int it = 0; it < CTX_NI; ++it) {
        const int buf = it % 3;
#pragma unroll
        for (int ks = 0; ks < 4; ks++) {
            uint32_t af[2][4], bq[2][4];
#pragma unroll
            for (int i = 0; i < 2; i++) ldsm_x4(af[i], aAddr[buf][i] + ks * 32);
#pragma unroll
            for (int jp = 0; jp < 2; jp++) ldsm_x4(bq[jp], bAddr[buf][jp] + ks * 32);
#pragma unroll
            for (int i = 0; i < 2; i++)
#pragma unroll
                for (int j = 0; j < 4; j++)
                    mma_f16(acc[i][j], af[i][0], af[i][1], af[i][2], af[i][3],
                            bq[j >> 1][(j & 1) * 2], bq[j >> 1][(j & 1) * 2 + 1]);
        }
        __syncthreads();
        if (it + 3 < CTX_NI) { prefetch(it + 3, buf); cp_commit(); }
        if (it + 1 < CTX_NI) {
            if (it + 3 < CTX_NI)       cp_wait<2>();
            else if (it + 2 < CTX_NI)  cp_wait<1>();
            else                       cp_wait<0>();
            __syncthreads();
        }
    }

    const float* invh = inv + (long)h * T_LEN;
#pragma unroll
    for (int i = 0; i < 2; i++) {
#pragma unroll
        for (int j = 0; j < 4; j++) {
#pragma unroll
            for (int h2 = 0; h2 < 2; h2++) {
                const int m = gm0 + wm0 + i*16 + gid + h2*8;
                const int n = h * HD + wn0 + j*8 + tg*2;
                const float sc = invh[m];
                float v0 = acc[i][j][h2*2 + 0] * sc;
                float v1 = acc[i][j][h2*2 + 1] * sc;
                *(__half2*)(CTX + (long)m * E_DIM + n) = __floats2half2_rn(v0, v1);
            }
        }
    }
}

// ===========================================================================
// Generic fp16-MMA GEMM (unchanged) — projections + out-projection.
// ===========================================================================
template<int BM, int BN, int WARPS_M, int WARPS_N,
         int EPI, bool AH, bool BH, bool NORMROW, bool CH>
__global__ __launch_bounds__(WARPS_M*WARPS_N*32)
void gemm_k(const void* __restrict__ Av, const void* __restrict__ Bv,
            const float* __restrict__ bias, void* __restrict__ Cv,
            const float* __restrict__ rowinv,
            int M, int N, int K, int ldc,
            long aH, long bH, long cH, long riH, float scale)
{
    constexpr int THREADS = WARPS_M*WARPS_N*32;
    constexpr int BK = 32;
    constexpr int WM = BM/WARPS_M, WN = BN/WARPS_N;
    constexpr int MT = WM/16, NT = WN/8;
    static_assert(NT % 2 == 0, "NT must be even");

    const float*  Af  = (const float*) Av + (AH ? 0 : blockIdx.z * aH);
    const __half* Ahp = (const __half*)Av + (AH ? blockIdx.z * aH : 0);
    const float*  Bf  = (const float*) Bv + (BH ? 0 : blockIdx.z * bH);
    const __half* Bhp = (const __half*)Bv + (BH ? blockIdx.z * bH : 0);
    float*  Cf  = (float*) Cv + (CH ? 0 : blockIdx.z * cH);
    __half* Chp = (__half*)Cv + (CH ? blockIdx.z * cH : 0);
    if (NORMROW) rowinv += blockIdx.z * riH;

    __shared__ __half As[2][BM][40];
    __shared__ __half Bs[2][BN][40];

    const int tid  = threadIdx.x;
    const int warp = tid >> 5, lane = tid & 31;
    const int wm0 = (warp / WARPS_N) * WM;
    const int wn0 = (warp % WARPS_N) * WN;
    const int gid = lane >> 2, tg = lane & 3;
    const int gm0 = blockIdx.y * BM, gn0 = blockIdx.x * BN;

    constexpr int AC = AH ? BM*BK/(THREADS*8) : BM*BK/(THREADS*4);
    constexpr int BC = BH ? BN*BK/(THREADS*8) : BN*BK/(THREADS*4);
    int am[AC], ak[AC], bn[BC], bk[BC];
#pragma unroll
    for (int i = 0; i < AC; i++) {
        int idx = (tid + i*THREADS) * (AH ? 8 : 4);
        am[i] = idx / BK; ak[i] = idx % BK;
    }
#pragma unroll
    for (int i = 0; i < BC; i++) {
        int idx = (tid + i*THREADS) * (BH ? 8 : 4);
        bn[i] = idx / BK; bk[i] = idx % BK;
    }

    constexpr uint32_t A_BUF = BM * 40 * 2;
    constexpr uint32_t B_BUF = BN * 40 * 2;
    uint32_t aAddr0[MT], bAddr0[NT/2];
#pragma unroll
    for (int i = 0; i < MT; i++)
        aAddr0[i] = smem_u32(&As[0][wm0 + i*16 + (lane & 15)][(lane >> 4) * 8]);
#pragma unroll
    for (int jp = 0; jp < NT/2; jp++)
        bAddr0[jp] = smem_u32(&Bs[0][wn0 + jp*16 + (lane & 7) + ((lane >> 4) << 3)]
                                 [((lane >> 3) & 1) * 8]);

    uint4  ra16[AC], rb16[BC];
    float4 ra32[AC], rb32[BC];
    auto loadg = [&](int k0) {
#pragma unroll
        for (int i = 0; i < AC; i++) {
            if (AH) ra16[i] = *(const uint4*)(Ahp + (long)(gm0 + am[i])*K + k0 + ak[i]);
            else    ra32[i] = *(const float4*)(Af + (long)(gm0 + am[i])*K + k0 + ak[i]);
        }
#pragma unroll
        for (int i = 0; i < BC; i++) {
            if (BH) rb16[i] = *(const uint4*)(Bhp + (long)(gn0 + bn[i])*K + k0 + bk[i]);
            else    rb32[i] = *(const float4*)(Bf + (long)(gn0 + bn[i])*K + k0 + bk[i]);
        }
    };
    auto sts = [&](int buf) {
#pragma unroll
        for (int i = 0; i < AC; i++) {
            if (AH) *(uint4*)&As[buf][am[i]][ak[i]] = ra16[i];
            else {
                __half2 lo = __floats2half2_rn(ra32[i].x, ra32[i].y);
                __half2 hi = __floats2half2_rn(ra32[i].z, ra32[i].w);
                *(__half2*)&As[buf][am[i]][ak[i]    ] = lo;
                *(__half2*)&As[buf][am[i]][ak[i] + 2] = hi;
            }
        }
#pragma unroll
        for (int i = 0; i < BC; i++) {
            if (BH) *(uint4*)&Bs[buf][bn[i]][bk[i]] = rb16[i];
            else {
                __half2 lo = __floats2half2_rn(rb32[i].x, rb32[i].y);
                __half2 hi = __floats2half2_rn(rb32[i].z, rb32[i].w);
                *(__half2*)&Bs[buf][bn[i]][bk[i]    ] = lo;
                *(__half2*)&Bs[buf][bn[i]][bk[i] + 2] = hi;
            }
        }
    };

    float acc[MT][NT][4];
#pragma unroll
    for (int i = 0; i < MT; i++)
#pragma unroll
        for (int j = 0; j < NT; j++)
#pragma unroll
            for (int q = 0; q < 4; q++) acc[i][j][q] = 0.0f;

    const int NI = K / BK;
    loadg(0);
    sts(0);
#pragma unroll 1
    for (int it = 0; it < NI; ++it) {
        __syncthreads();
        if (it + 1 < NI) loadg((it + 1) * BK);
        const int buf = it & 1;
        const uint32_t aB = buf * A_BUF, bB = buf * B_BUF;
#pragma unroll
        for (int ks = 0; ks < BK; ks += 16) {
            uint32_t af[MT][4], bq[NT/2][4];
#pragma unroll
            for (int i = 0; i < MT; i++) ldsm_x4(af[i], aAddr0[i] + aB + ks * 2);
#pragma unroll
            for (int jp = 0; jp < NT/2; jp++) ldsm_x4(bq[jp], bAddr0[jp] + bB + ks * 2);
#pragma unroll
            for (int i = 0; i < MT; i++)
#pragma unroll
                for (int j = 0; j < NT; j++)
                    mma_f16(acc[i][j], af[i][0], af[i][1], af[i][2], af[i][3],
                            bq[j >> 1][(j & 1) * 2], bq[j >> 1][(j & 1) * 2 + 1]);
        }
        if (it + 1 < NI) sts(buf ^ 1);
    }

#pragma unroll
    for (int i = 0; i < MT; i++) {
#pragma unroll
        for (int j = 0; j < NT; j++) {
#pragma unroll
            for (int h2 = 0; h2 < 2; h2++) {
                int m = gm0 + wm0 + i*16 + gid + h2*8;
                int n = gn0 + wn0 + j*8 + tg*2;
                float v0 = acc[i][j][h2*2 + 0];
                float v1 = acc[i][j][h2*2 + 1];
                if (bias) { v0 += bias[n]; v1 += bias[n+1]; }
                float sc = NORMROW ? rowinv[m] : scale;
                v0 *= sc; v1 *= sc;
                if (EPI == 0) {
                    if (CH) *(__half2*)(Chp + (long)m*ldc + n) = __floats2half2_rn(v0, v1);
                    else    *(float2*)(Cf + (long)m*ldc + n) = make_float2(v0, v1);
                } else if (EPI == 1) {
                    int h = n >> 6, d = n & 63;
                    *(__half2*)(Chp + (long)h*M*HD + (long)m*HD + d) =
                        __floats2half2_rn(v0, v1);
                } else {
                    int h = n >> 6, d = n & 63;
                    __half* p = Chp + (long)h*HD*M + (long)d*M + m;
                    p[0] = __float2half_rn(v0);
                    p[M] = __float2half_rn(v1);
                }
            }
        }
    }
}

// ---------------------------------------------------------------------------
__global__ __launch_bounds__(256) void invred_k(const float* __restrict__ part,
                                                float* __restrict__ inv)
{
    const long row = (long)blockIdx.x * 256 + threadIdx.x;
    const float4 p = ((const float4*)part)[row];
    inv[row] = 1.0f / ((p.x + p.y) + (p.z + p.w));
}

// ---------------------------------------------------------------------------
__global__ __launch_bounds__(1024) void avg_k(const __half* __restrict__ P,
                                              const float* __restrict__ inv,
                                              float* __restrict__ out)
{
    const int t = blockIdx.x, tid = threadIdx.x;
    const long TS = (long)T_LEN * T_LEN;
    const __half* base = P + (long)t * T_LEN + tid * 4;
    float4 acc = make_float4(0.f, 0.f, 0.f, 0.f);
#pragma unroll
    for (int h = 0; h < H_NUM; h++) {
        const float iv = inv[h * T_LEN + t] * (1.0f / H_NUM);
        uint2 u = *(const uint2*)(base + (long)h * TS);
        float2 lo = __half22float2(*(__half2*)&u.x);
        float2 hi = __half22float2(*(__half2*)&u.y);
        acc.x += lo.x * iv; acc.y += lo.y * iv;
        acc.z += hi.x * iv; acc.w += hi.y * iv;
    }
    ((float4*)(out + (long)t * T_LEN))[tid] = acc;
}

// ---------------------------------------------------------------------------
extern "C" void kernel_launch(void* const* d_in, const int* in_sizes, int n_in,
                              void* d_out, int out_size)
{
    const float* q_in = (const float*)d_in[0];
    const float* k_in = (const float*)d_in[1];
    const float* v_in = (const float*)d_in[2];
    const float* w    = (const float*)d_in[3];
    const float* b    = (const float*)d_in[4];
    const float* ow   = (const float*)d_in[5];
    const float* ob   = (const float*)d_in[6];
    float* out = (float*)d_out;

    __half *Q, *K, *Vt, *P, *CTX;
    float *RSP, *INV;
    cudaGetSymbolAddress((void**)&Q,   g_Q);
    cudaGetSymbolAddress((void**)&K,   g_K);
    cudaGetSymbolAddress((void**)&Vt,  g_Vt);
    cudaGetSymbolAddress((void**)&P,   g_P);
    cudaGetSymbolAddress((void**)&CTX, g_CTX);
    cudaGetSymbolAddress((void**)&RSP, g_RSP);
    cudaGetSymbolAddress((void**)&INV, g_INV);

    const int T = T_LEN, E = E_DIM, H = H_NUM;
    const long EE = (long)E * E;
    dim3 blk(256);

    // QKV projections: fp32 in -> fp16 head-major out
    gemm_k<128,128,2,4,1,false,false,false,true><<<dim3(E/128, T/128, 1), blk>>>(
        q_in, w,        b,       Q,  nullptr, T, E, E, 0, 0,0,0,0, 0.125f);
    gemm_k<128,128,2,4,1,false,false,false,true><<<dim3(E/128, T/128, 1), blk>>>(
        k_in, w + EE,   b + E,   K,  nullptr, T, E, E, 0, 0,0,0,0, 1.0f);
    gemm_k<128,128,2,4,2,false,false,false,true><<<dim3(E/128, T/128, 1), blk>>>(
        v_in, w + 2*EE, b + 2*E, Vt, nullptr, T, E, E, 0, 0,0,0,0, 1.0f);

    // scores (pipelined, STG.128 epilogue) -> fp16 P + partial row sums
    scores_k<<<dim3(NBX_SCORES, T/128, H), blk>>>(Q, K, P, RSP);

    // row-sum reduce -> inv
    invred_k<<<(H*T)/256, 256>>>(RSP, INV);

    // head-average -> second half of d_out
    avg_k<<<T, 1024>>>(P, INV, out + (long)T * E);

    // ctx (dedicated pipelined kernel)
    ctx_k<<<dim3(T/128, H), blk>>>(P, Vt, INV, CTX);

    // out projection: fp16 CTX @ fp32 W^T + bias -> fp32 out
    gemm_k<128,128,2,4,0,true,false,false,false><<<dim3(E/128, T/128, 1), blk>>>(
        CTX, ow, ob, out, nullptr, T, E, E, E, 0,0,0,0, 1.0f);
}